// round 3
// baseline (speedup 1.0000x reference)
#include <cuda_runtime.h>

// EgoAttentionNetwork: B=8192, E=64, F_IN=7, D=64, H=4, HD=16
// One CTA per batch element, 256 threads, fully fused.
// Key ideas:
//  - mask compaction (exact): softmax weight of masked entities is exactly 0
//    in fp32, so skip their MLP/K/V. All-masked -> uniform 1/64 fallback.
//  - packed fp32x2 FMA in the three 64x64 GEMM passes.
//  - activations stored transposed (feature-major, stride 66) so GEMM loads
//    entity pairs as float2; weights staged in smem per pass.

typedef unsigned long long u64;

#define AST 66           // activation row stride (even for f32x2, 66%32=2 -> low conflicts)
#define NTHR 256
#define FULLMASK 0xffffffffu

__device__ __forceinline__ u64 fma2(u64 a, u64 b, u64 c) {
    u64 d;
    asm("fma.rn.f32x2 %0, %1, %2, %3;" : "=l"(d) : "l"(a), "l"(b), "l"(c));
    return d;
}
__device__ __forceinline__ u64 dup2(float x) {
    u64 r;
    asm("mov.b64 %0, {%1, %1};" : "=l"(r) : "f"(x));
    return r;
}
__device__ __forceinline__ float2 unpack2(u64 v) {
    float2 r;
    asm("mov.b64 {%0, %1}, %2;" : "=f"(r.x), "=f"(r.y) : "l"(v));
    return r;
}

struct SmemT {
    float hT[64 * AST];     // hidden^T; reused as K^T, then V^T
    float aT[64 * AST];     // input_all^T (compacted columns)
    float sW[64 * 64];      // staged weight matrix (oth_w1 -> Wk -> Wv)
    float sX[64 * 8];       // raw x rows, padded to 8
    float h0[64];           // ego hidden
    float sEgo[64];         // ego embedding
    float sQ[64];           // query
    float sO[64];           // attention output
    float sS[4 * 64];       // scores
    float sP[4 * 64];       // probs
    int   sIdx[64];         // compacted active-other entity ids
    int   nOth, uniformF, egoAct;
};

// C^T[d][e] = sum_k A^T[k][e] * W[k][d]  (+bias, +relu optional)
// Thread tile: 4 entities x 4 features; weights from smem (float4),
// activations as float2 entity pairs (fp32x2 FMA).
__device__ __forceinline__ void gemm64(const float* __restrict__ AT,
                                       const float* __restrict__ sW,
                                       const float* __restrict__ bias_g,
                                       float* __restrict__ CT,
                                       int nTiles, int rot, int tid, bool doRelu)
{
    const int dt = tid & 15;
    const int et = ((tid >> 4) + rot) & 15;
    if (et >= nTiles) return;
    const int e0 = et * 4, d0 = dt * 4;

    u64 a00 = 0, a01 = 0, a10 = 0, a11 = 0, a20 = 0, a21 = 0, a30 = 0, a31 = 0;
    const float4* W4 = reinterpret_cast<const float4*>(sW);

    #pragma unroll 4
    for (int k = 0; k < 64; k++) {
        const float* ar = AT + k * AST + e0;
        u64 p01 = *reinterpret_cast<const u64*>(ar);
        u64 p23 = *reinterpret_cast<const u64*>(ar + 2);
        float4 w = W4[k * 16 + dt];
        u64 wx = dup2(w.x), wy = dup2(w.y), wz = dup2(w.z), ww = dup2(w.w);
        a00 = fma2(p01, wx, a00);  a01 = fma2(p23, wx, a01);
        a10 = fma2(p01, wy, a10);  a11 = fma2(p23, wy, a11);
        a20 = fma2(p01, wz, a20);  a21 = fma2(p23, wz, a21);
        a30 = fma2(p01, ww, a30);  a31 = fma2(p23, ww, a31);
    }

    u64 acc[4][2] = {{a00, a01}, {a10, a11}, {a20, a21}, {a30, a31}};
    #pragma unroll
    for (int j = 0; j < 4; j++) {
        float2 c01 = unpack2(acc[j][0]);
        float2 c23 = unpack2(acc[j][1]);
        const int d = d0 + j;
        if (bias_g) {
            float bb = __ldg(bias_g + d);
            c01.x += bb; c01.y += bb; c23.x += bb; c23.y += bb;
        }
        if (doRelu) {
            c01.x = fmaxf(c01.x, 0.f); c01.y = fmaxf(c01.y, 0.f);
            c23.x = fmaxf(c23.x, 0.f); c23.y = fmaxf(c23.y, 0.f);
        }
        float* cr = CT + d * AST + e0;
        *reinterpret_cast<float2*>(cr)     = c01;
        *reinterpret_cast<float2*>(cr + 2) = c23;
    }
}

__global__ void __launch_bounds__(NTHR, 4)
ego_attn_kernel(const float* __restrict__ x,
                const float* __restrict__ ego_w0, const float* __restrict__ ego_b0,
                const float* __restrict__ ego_w1, const float* __restrict__ ego_b1,
                const float* __restrict__ oth_w0, const float* __restrict__ oth_b0,
                const float* __restrict__ oth_w1, const float* __restrict__ oth_b1,
                const float* __restrict__ Wk, const float* __restrict__ Wv,
                const float* __restrict__ Wq, const float* __restrict__ Wc,
                float* __restrict__ out)
{
    extern __shared__ char smem_raw[];
    SmemT* s = reinterpret_cast<SmemT*>(smem_raw);
    const int tid = threadIdx.x;
    const int b = blockIdx.x;
    const int rot = b & 15;
    const float* xb = x + b * 64 * 7;

    // ---- P1: load x into padded smem ----
    for (int idx = tid; idx < 448; idx += NTHR) {
        int e = idx / 7, f = idx % 7;
        s->sX[e * 8 + f] = __ldg(xb + idx);
    }
    __syncthreads();

    // ---- P2: warp0 compaction | warp1 ego layer0 | warps 2-7 stage oth_w1 ----
    if (tid < 32) {
        const int lane = tid;
        int egoA = (s->sX[0] >= 0.5f) ? 1 : 0;
        unsigned m1 = __ballot_sync(FULLMASK, (lane >= 1) && (s->sX[lane * 8] >= 0.5f));
        unsigned m2 = __ballot_sync(FULLMASK, s->sX[(lane + 32) * 8] >= 0.5f);
        int cnt = __popc(m1) + __popc(m2);
        unsigned lmask = (1u << lane) - 1u;
        if (cnt == 0 && !egoA) {
            // all 64 entities masked -> uniform attention over all of them
            s->sIdx[lane] = lane + 1;
            if (lane < 31) s->sIdx[lane + 32] = lane + 33;
            if (lane == 0) { s->nOth = 63; s->uniformF = 1; s->egoAct = egoA; }
        } else {
            if ((lane >= 1) && (m1 >> lane & 1u))
                s->sIdx[__popc(m1 & lmask)] = lane;
            if (m2 >> lane & 1u)
                s->sIdx[__popc(m1) + __popc(m2 & lmask)] = lane + 32;
            if (lane == 0) { s->nOth = cnt; s->uniformF = 0; s->egoAct = egoA; }
        }
    } else if (tid < 64) {
        const int lane = tid - 32;
        #pragma unroll
        for (int r = 0; r < 2; r++) {
            int d = lane + r * 32;
            float acc = __ldg(ego_b0 + d);
            #pragma unroll
            for (int f = 0; f < 7; f++)
                acc += s->sX[f] * __ldg(ego_w0 + f * 64 + d);
            s->h0[d] = fmaxf(acc, 0.f);
        }
    } else {
        const float4* W4 = reinterpret_cast<const float4*>(oth_w1);
        float4* D4 = reinterpret_cast<float4*>(s->sW);
        for (int idx = tid - 64; idx < 1024; idx += 192) D4[idx] = __ldg(W4 + idx);
    }
    __syncthreads();

    const int nOth = s->nOth;
    const int uniformF = s->uniformF;
    const int egoAct = s->egoAct;
    const int cEgo = nOth;
    const int nTot = nOth + 1;
    int PADMAX = (nTot + 3) & ~3;  if (PADMAX > 64) PADMAX = 64;
    const int nTiles = PADMAX >> 2;

    // ---- P3: others layer0 (compacted, transposed) + ego layer1 ----
    for (int idx = tid; idx < 4096; idx += NTHR) {
        int i = idx & 63, d = idx >> 6;
        float v = 0.f;
        if (i < nOth) {
            int e = s->sIdx[i];
            float acc = __ldg(oth_b0 + d);
            #pragma unroll
            for (int f = 0; f < 7; f++)
                acc += s->sX[e * 8 + f] * __ldg(oth_w0 + f * 64 + d);
            v = fmaxf(acc, 0.f);
        }
        s->hT[d * AST + i] = v;
    }
    if (tid < 64) {
        const int d = tid;
        float a0 = __ldg(ego_b1 + d), a1 = 0.f, a2 = 0.f, a3 = 0.f;
        #pragma unroll 4
        for (int k = 0; k < 64; k += 4) {
            a0 += s->h0[k]     * __ldg(ego_w1 + (k)     * 64 + d);
            a1 += s->h0[k + 1] * __ldg(ego_w1 + (k + 1) * 64 + d);
            a2 += s->h0[k + 2] * __ldg(ego_w1 + (k + 2) * 64 + d);
            a3 += s->h0[k + 3] * __ldg(ego_w1 + (k + 3) * 64 + d);
        }
        s->sEgo[d] = fmaxf((a0 + a1) + (a2 + a3), 0.f);
    }
    __syncthreads();

    // ---- P4: others layer1 GEMM: hT -> aT (bias+relu) ----
    gemm64(s->hT, s->sW, oth_b1, s->aT, nTiles, rot, tid, true);
    __syncthreads();

    // ---- P5: stage Wk | write ego column into aT + compute q ----
    if (tid < 192) {
        const float4* W4 = reinterpret_cast<const float4*>(Wk);
        float4* D4 = reinterpret_cast<float4*>(s->sW);
        for (int idx = tid; idx < 1024; idx += 192) D4[idx] = __ldg(W4 + idx);
    } else {
        const int d = tid - 192;
        s->aT[d * AST + cEgo] = s->sEgo[d];
        float a0 = 0.f, a1 = 0.f, a2 = 0.f, a3 = 0.f;
        #pragma unroll 4
        for (int k = 0; k < 64; k += 4) {
            a0 += s->sEgo[k]     * __ldg(Wq + (k)     * 64 + d);
            a1 += s->sEgo[k + 1] * __ldg(Wq + (k + 1) * 64 + d);
            a2 += s->sEgo[k + 2] * __ldg(Wq + (k + 2) * 64 + d);
            a3 += s->sEgo[k + 3] * __ldg(Wq + (k + 3) * 64 + d);
        }
        s->sQ[d] = (a0 + a1) + (a2 + a3);
    }
    __syncthreads();

    // ---- P6: K GEMM: aT -> hT (=K^T) ----
    gemm64(s->aT, s->sW, nullptr, s->hT, nTiles, rot, tid, false);
    __syncthreads();

    // ---- P7: scores (all threads, one (head, col) each) + stage Wv ----
    {
        const int h = tid >> 6, i = tid & 63;
        bool part = uniformF ? (i < nTot)
                             : ((i < nOth) || (i == cEgo && egoAct));
        float sc = -1e30f;
        if (part) {
            float a0 = 0.f, a1 = 0.f;
            #pragma unroll
            for (int j = 0; j < 16; j += 2) {
                a0 += s->sQ[h * 16 + j]     * s->hT[(h * 16 + j)     * AST + i];
                a1 += s->sQ[h * 16 + j + 1] * s->hT[(h * 16 + j + 1) * AST + i];
            }
            sc = (a0 + a1) * 0.25f;   // 1/sqrt(HD)
        }
        s->sS[h * 64 + i] = sc;
    }
    {
        const float4* W4 = reinterpret_cast<const float4*>(Wv);
        float4* D4 = reinterpret_cast<float4*>(s->sW);
        for (int idx = tid; idx < 1024; idx += NTHR) D4[idx] = __ldg(W4 + idx);
    }
    __syncthreads();

    // ---- P8: softmax per head (warps 0-3) ----
    if (tid < 128) {
        const int h = tid >> 5, lane = tid & 31;
        if (uniformF) {
            const float p = 1.0f / 64.0f;
            s->sP[h * 64 + lane] = p;
            s->sP[h * 64 + lane + 32] = p;
        } else {
            float s0 = s->sS[h * 64 + lane];
            float s1 = s->sS[h * 64 + lane + 32];
            float m = fmaxf(s0, s1);
            #pragma unroll
            for (int off = 16; off; off >>= 1)
                m = fmaxf(m, __shfl_xor_sync(FULLMASK, m, off));
            float e0 = __expf(s0 - m);
            float e1 = __expf(s1 - m);
            float sum = e0 + e1;
            #pragma unroll
            for (int off = 16; off; off >>= 1)
                sum += __shfl_xor_sync(FULLMASK, sum, off);
            float inv = 1.0f / sum;
            s->sP[h * 64 + lane] = e0 * inv;
            s->sP[h * 64 + lane + 32] = e1 * inv;
        }
    }
    __syncthreads();

    // ---- P9: V GEMM: aT -> hT (=V^T; K^T consumed) ----
    gemm64(s->aT, s->sW, nullptr, s->hT, nTiles, rot, tid, false);
    __syncthreads();

    // ---- P10: attention-weighted sum ----
    if (tid < 64) {
        const int d = tid, h = d >> 4;
        const float* pr = s->sP + h * 64;
        const float* vr = s->hT + d * AST;
        float a0 = 0.f, a1 = 0.f, a2 = 0.f, a3 = 0.f;
        for (int i = 0; i < PADMAX; i += 4) {
            a0 += pr[i]     * vr[i];
            a1 += pr[i + 1] * vr[i + 1];
            a2 += pr[i + 2] * vr[i + 2];
            a3 += pr[i + 3] * vr[i + 3];
        }
        s->sO[d] = (a0 + a1) + (a2 + a3);
    }
    __syncthreads();

    // ---- P11: epilogue: (out @ Wc + ego) * 0.5 ----
    if (tid < 64) {
        const int d = tid;
        float a0 = 0.f, a1 = 0.f, a2 = 0.f, a3 = 0.f;
        #pragma unroll 4
        for (int k = 0; k < 64; k += 4) {
            a0 += s->sO[k]     * __ldg(Wc + (k)     * 64 + d);
            a1 += s->sO[k + 1] * __ldg(Wc + (k + 1) * 64 + d);
            a2 += s->sO[k + 2] * __ldg(Wc + (k + 2) * 64 + d);
            a3 += s->sO[k + 3] * __ldg(Wc + (k + 3) * 64 + d);
        }
        out[b * 64 + d] = (((a0 + a1) + (a2 + a3)) + s->sEgo[d]) * 0.5f;
    }
}

extern "C" void kernel_launch(void* const* d_in, const int* in_sizes, int n_in,
                              void* d_out, int out_size) {
    (void)in_sizes; (void)n_in; (void)out_size;
    const float* x      = (const float*)d_in[0];
    const float* ego_w0 = (const float*)d_in[1];
    const float* ego_b0 = (const float*)d_in[2];
    const float* ego_w1 = (const float*)d_in[3];
    const float* ego_b1 = (const float*)d_in[4];
    const float* oth_w0 = (const float*)d_in[5];
    const float* oth_b0 = (const float*)d_in[6];
    const float* oth_w1 = (const float*)d_in[7];
    const float* oth_b1 = (const float*)d_in[8];
    const float* Wk     = (const float*)d_in[9];
    const float* Wv     = (const float*)d_in[10];
    const float* Wq     = (const float*)d_in[11];
    const float* Wc     = (const float*)d_in[12];
    float* out = (float*)d_out;

    const int smem = (int)sizeof(SmemT);
    cudaFuncSetAttribute(ego_attn_kernel,
                         cudaFuncAttributeMaxDynamicSharedMemorySize, smem);
    ego_attn_kernel<<<8192, NTHR, smem>>>(x, ego_w0, ego_b0, ego_w1, ego_b1,
                                          oth_w0, oth_b0, oth_w1, oth_b1,
                                          Wk, Wv, Wq, Wc, out);
}

// round 4
// speedup vs baseline: 1.1069x; 1.1069x over previous
#include <cuda_runtime.h>

// EgoAttentionNetwork: B=8192, E=64, F_IN=7, D=64, H=4, HD=16
// One CTA per batch, 256 threads, fully fused. Round-3 design:
//  - mask compaction (exact, softmax weight of masked entities is 0.0f)
//  - no smem weight staging: weights via __ldg, L1-resident across CTAs
//  - GEMM A-operand = single LDS.128 (AST=68); fp32x2 FMAs
//  - K GEMM keeps K in registers and emits scores directly (shfl reduce)
//  - V GEMM keeps V in registers and emits P-weighted sums via smem atomics

typedef unsigned long long u64;

#define AST 68
#define NTHR 256
#define FULLMASK 0xffffffffu

static __device__ __forceinline__ u64 fma2(u64 a, u64 b, u64 c) {
    u64 d;
    asm("fma.rn.f32x2 %0, %1, %2, %3;" : "=l"(d) : "l"(a), "l"(b), "l"(c));
    return d;
}
static __device__ __forceinline__ u64 dup2(float x) {
    u64 r;
    asm("mov.b64 %0, {%1, %1};" : "=l"(r) : "f"(x));
    return r;
}
static __device__ __forceinline__ float2 unpack2(u64 v) {
    float2 r;
    asm("mov.b64 {%0, %1}, %2;" : "=f"(r.x), "=f"(r.y) : "l"(v));
    return r;
}
static __device__ __forceinline__ void loadA(const float* p, u64& a, u64& b) {
    float4 v = *reinterpret_cast<const float4*>(p);
    asm("mov.b64 %0, {%1, %2};" : "=l"(a) : "f"(v.x), "f"(v.y));
    asm("mov.b64 %0, {%1, %2};" : "=l"(b) : "f"(v.z), "f"(v.w));
}

struct __align__(16) SmemT {
    float hT[64 * AST];   // hidden^T (others layer0 out)
    float aT[64 * AST];   // input_all^T
    float sX[64 * 8];     // raw x rows (padded)
    float h0[64];         // ego hidden
    float sEgo[64];       // ego embedding
    float sQ[64];         // query
    float sO[64];         // attention out (atomic accum)
    float sS[256];        // scores [4 heads][64]
    float sP[256];        // probs
    int   sIdx[64];
    int   nOth, uniformF, egoAct;
};

__global__ void __launch_bounds__(NTHR, 4)
ego_attn_kernel(const float* __restrict__ x,
                const float* __restrict__ ego_w0, const float* __restrict__ ego_b0,
                const float* __restrict__ ego_w1, const float* __restrict__ ego_b1,
                const float* __restrict__ oth_w0, const float* __restrict__ oth_b0,
                const float* __restrict__ oth_w1, const float* __restrict__ oth_b1,
                const float* __restrict__ Wk, const float* __restrict__ Wv,
                const float* __restrict__ Wq, const float* __restrict__ Wc,
                float* __restrict__ out)
{
    __shared__ SmemT s;
    const int tid = threadIdx.x;
    const int b = blockIdx.x;
    const int rot = b & 15;
    const int dt = tid & 15;
    const int etr = ((tid >> 4) + rot) & 15;   // rotated entity-tile id
    const float* xb = x + b * 448;

    // ---- PH1: load x, init score/out buffers ----
    for (int idx = tid; idx < 448; idx += NTHR) {
        int e = idx / 7, f = idx % 7;
        s.sX[e * 8 + f] = __ldg(xb + idx);
    }
    s.sS[tid] = -1e30f;
    if (tid < 64) s.sO[tid] = 0.f;
    __syncthreads();

    // ---- PH2: compaction (warp0) | ego layer0 (warp1) ----
    if (tid < 32) {
        const int lane = tid;
        int egoA = (s.sX[0] >= 0.5f) ? 1 : 0;
        unsigned m1 = __ballot_sync(FULLMASK, (lane >= 1) && (s.sX[lane * 8] >= 0.5f));
        unsigned m2 = __ballot_sync(FULLMASK, s.sX[(lane + 32) * 8] >= 0.5f);
        int cnt = __popc(m1) + __popc(m2);
        unsigned lmask = (1u << lane) - 1u;
        if (cnt == 0 && !egoA) {
            // all masked -> uniform softmax over all 64 entities
            s.sIdx[lane] = lane + 1;
            if (lane < 31) s.sIdx[lane + 32] = lane + 33;
            if (lane == 0) { s.nOth = 63; s.uniformF = 1; s.egoAct = egoA; }
        } else {
            if ((lane >= 1) && (m1 >> lane & 1u))
                s.sIdx[__popc(m1 & lmask)] = lane;
            if (m2 >> lane & 1u)
                s.sIdx[__popc(m1) + __popc(m2 & lmask)] = lane + 32;
            if (lane == 0) { s.nOth = cnt; s.uniformF = 0; s.egoAct = egoA; }
        }
    } else if (tid < 64) {
        const int lane = tid - 32;
        #pragma unroll
        for (int r = 0; r < 2; r++) {
            int d = lane + r * 32;
            float acc = __ldg(ego_b0 + d);
            #pragma unroll
            for (int f = 0; f < 7; f++)
                acc += s.sX[f] * __ldg(ego_w0 + f * 64 + d);
            s.h0[d] = fmaxf(acc, 0.f);
        }
    }
    __syncthreads();

    const int nOth = s.nOth;
    const int uniformF = s.uniformF;
    const int egoAct = s.egoAct;
    const int cEgo = nOth;
    const int nTot = nOth + 1;
    int PADMAX = (nTot + 3) & ~3; if (PADMAX > 64) PADMAX = 64;
    const int nTiles = PADMAX >> 2;

    // ---- PH3: others layer0 (compacted, d-pairs) | ego layer1 ----
    if (tid < 192) {
        const int total = nOth * 32;
        for (int idx = tid; idx < total; idx += 192) {
            int i = idx >> 5, d = (idx & 31) * 2;
            int e = s.sIdx[i];
            const float* xr = s.sX + e * 8;
            float2 bb = *reinterpret_cast<const float2*>(oth_b0 + d);
            float ax = bb.x, ay = bb.y;
            #pragma unroll
            for (int f = 0; f < 7; f++) {
                float2 w = __ldg(reinterpret_cast<const float2*>(oth_w0 + f * 64 + d));
                float xv = xr[f];
                ax += xv * w.x; ay += xv * w.y;
            }
            s.hT[d * AST + i]       = fmaxf(ax, 0.f);
            s.hT[(d + 1) * AST + i] = fmaxf(ay, 0.f);
        }
    } else {
        const int d = tid - 192;
        float a0 = __ldg(ego_b1 + d), a1 = 0.f, a2 = 0.f, a3 = 0.f;
        #pragma unroll 4
        for (int k = 0; k < 64; k += 4) {
            a0 += s.h0[k]     * __ldg(ego_w1 + (k)     * 64 + d);
            a1 += s.h0[k + 1] * __ldg(ego_w1 + (k + 1) * 64 + d);
            a2 += s.h0[k + 2] * __ldg(ego_w1 + (k + 2) * 64 + d);
            a3 += s.h0[k + 3] * __ldg(ego_w1 + (k + 3) * 64 + d);
        }
        s.sEgo[d] = fmaxf((a0 + a1) + (a2 + a3), 0.f);
    }
    // zero-fill hT columns [nOth, PADMAX)
    if (tid < 64) {
        for (int c = nOth; c < PADMAX; c++) s.hT[tid * AST + c] = 0.f;
    }
    __syncthreads();

    // ---- PH4: others layer1 GEMM (hT -> aT, bias+relu, ego-col patch)
    //          free threads compute q ----
    const bool gact = (etr < nTiles);
    const bool canFreeQ = (nTiles <= 12);
    if (gact) {
        const int e0 = etr * 4, d0 = dt * 4;
        u64 a00 = 0, a01 = 0, a10 = 0, a11 = 0, a20 = 0, a21 = 0, a30 = 0, a31 = 0;
        #pragma unroll 4
        for (int k = 0; k < 64; k++) {
            u64 p01, p23; loadA(s.hT + k * AST + e0, p01, p23);
            float4 w = __ldg(reinterpret_cast<const float4*>(oth_w1 + k * 64) + dt);
            u64 wx = dup2(w.x), wy = dup2(w.y), wz = dup2(w.z), ww = dup2(w.w);
            a00 = fma2(p01, wx, a00);  a01 = fma2(p23, wx, a01);
            a10 = fma2(p01, wy, a10);  a11 = fma2(p23, wy, a11);
            a20 = fma2(p01, wz, a20);  a21 = fma2(p23, wz, a21);
            a30 = fma2(p01, ww, a30);  a31 = fma2(p23, ww, a31);
        }
        u64 acc[4][2] = {{a00, a01}, {a10, a11}, {a20, a21}, {a30, a31}};
        const int patch = cEgo - e0;   // 0..3 if ego col in this tile
        #pragma unroll
        for (int j = 0; j < 4; j++) {
            const int d = d0 + j;
            float bb = __ldg(oth_b1 + d);
            float2 c01 = unpack2(acc[j][0]);
            float2 c23 = unpack2(acc[j][1]);
            float eg = s.sEgo[d];
            float v0 = fmaxf(c01.x + bb, 0.f);
            float v1 = fmaxf(c01.y + bb, 0.f);
            float v2 = fmaxf(c23.x + bb, 0.f);
            float v3 = fmaxf(c23.y + bb, 0.f);
            if (patch == 0) v0 = eg;
            if (patch == 1) v1 = eg;
            if (patch == 2) v2 = eg;
            if (patch == 3) v3 = eg;
            *reinterpret_cast<float4*>(s.aT + d * AST + e0) =
                make_float4(v0, v1, v2, v3);
        }
    } else if (canFreeQ) {
        const int fr = etr - nTiles;
        if (fr < 4) {
            const int d = fr * 16 + dt;
            float a0 = 0.f, a1 = 0.f, a2 = 0.f, a3 = 0.f;
            #pragma unroll 4
            for (int k = 0; k < 64; k += 4) {
                a0 += s.sEgo[k]     * __ldg(Wq + (k)     * 64 + d);
                a1 += s.sEgo[k + 1] * __ldg(Wq + (k + 1) * 64 + d);
                a2 += s.sEgo[k + 2] * __ldg(Wq + (k + 2) * 64 + d);
                a3 += s.sEgo[k + 3] * __ldg(Wq + (k + 3) * 64 + d);
            }
            s.sQ[d] = (a0 + a1) + (a2 + a3);
        }
    }
    __syncthreads();
    if (!canFreeQ) {   // rare: nearly-full entity set
        if (tid < 64) {
            const int d = tid;
            float a0 = 0.f, a1 = 0.f, a2 = 0.f, a3 = 0.f;
            #pragma unroll 4
            for (int k = 0; k < 64; k += 4) {
                a0 += s.sEgo[k]     * __ldg(Wq + (k)     * 64 + d);
                a1 += s.sEgo[k + 1] * __ldg(Wq + (k + 1) * 64 + d);
                a2 += s.sEgo[k + 2] * __ldg(Wq + (k + 2) * 64 + d);
                a3 += s.sEgo[k + 3] * __ldg(Wq + (k + 3) * 64 + d);
            }
            s.sQ[d] = (a0 + a1) + (a2 + a3);
        }
        __syncthreads();
    }

    // ---- PH5: K GEMM in registers + direct score emit ----
    {
        unsigned amask = __ballot_sync(FULLMASK, gact);
        if (gact) {
            const int e0 = etr * 4, d0 = dt * 4;
            u64 a0k[2] = {0, 0}, a1k[2] = {0, 0}, a2k[2] = {0, 0}, a3k[2] = {0, 0};
            #pragma unroll 4
            for (int k = 0; k < 64; k++) {
                u64 p01, p23; loadA(s.aT + k * AST + e0, p01, p23);
                float4 w = __ldg(reinterpret_cast<const float4*>(Wk + k * 64) + dt);
                u64 wx = dup2(w.x), wy = dup2(w.y), wz = dup2(w.z), ww = dup2(w.w);
                a0k[0] = fma2(p01, wx, a0k[0]);  a0k[1] = fma2(p23, wx, a0k[1]);
                a1k[0] = fma2(p01, wy, a1k[0]);  a1k[1] = fma2(p23, wy, a1k[1]);
                a2k[0] = fma2(p01, wz, a2k[0]);  a2k[1] = fma2(p23, wz, a2k[1]);
                a3k[0] = fma2(p01, ww, a3k[0]);  a3k[1] = fma2(p23, ww, a3k[1]);
            }
            // score partials: sum_j q[d0+j] * K[d0+j][e0..e0+3]
            u64 s01 = 0, s23 = 0;
            {
                u64 q0 = dup2(s.sQ[d0]),     q1 = dup2(s.sQ[d0 + 1]);
                u64 q2 = dup2(s.sQ[d0 + 2]), q3 = dup2(s.sQ[d0 + 3]);
                s01 = fma2(a0k[0], q0, s01);  s23 = fma2(a0k[1], q0, s23);
                s01 = fma2(a1k[0], q1, s01);  s23 = fma2(a1k[1], q1, s23);
                s01 = fma2(a2k[0], q2, s01);  s23 = fma2(a2k[1], q2, s23);
                s01 = fma2(a3k[0], q3, s01);  s23 = fma2(a3k[1], q3, s23);
            }
            float2 f01 = unpack2(s01), f23 = unpack2(s23);
            float sc0 = f01.x, sc1 = f01.y, sc2 = f23.x, sc3 = f23.y;
            // reduce over the 4 dt lanes of this head (lanes xor 1, xor 2)
            sc0 += __shfl_xor_sync(amask, sc0, 1);
            sc1 += __shfl_xor_sync(amask, sc1, 1);
            sc2 += __shfl_xor_sync(amask, sc2, 1);
            sc3 += __shfl_xor_sync(amask, sc3, 1);
            sc0 += __shfl_xor_sync(amask, sc0, 2);
            sc1 += __shfl_xor_sync(amask, sc1, 2);
            sc2 += __shfl_xor_sync(amask, sc2, 2);
            sc3 += __shfl_xor_sync(amask, sc3, 2);
            if ((dt & 3) == 0) {
                const int h = dt >> 2;
                float scv[4] = {sc0, sc1, sc2, sc3};
                #pragma unroll
                for (int m = 0; m < 4; m++) {
                    int col = e0 + m;
                    bool act = uniformF ? (col < nTot)
                                        : ((col < nOth) || (col == cEgo && egoAct));
                    s.sS[h * 64 + col] = act ? scv[m] * 0.25f : -1e30f;
                }
            }
        }
    }
    __syncthreads();

    // ---- PH6: softmax per head (warps 0-3) ----
    if (tid < 128) {
        const int h = tid >> 5, lane = tid & 31;
        if (uniformF) {
            const float p = 1.0f / 64.0f;
            s.sP[h * 64 + lane] = p;
            s.sP[h * 64 + lane + 32] = p;
        } else {
            float s0 = s.sS[h * 64 + lane];
            float s1 = s.sS[h * 64 + lane + 32];
            float m = fmaxf(s0, s1);
            #pragma unroll
            for (int off = 16; off; off >>= 1)
                m = fmaxf(m, __shfl_xor_sync(FULLMASK, m, off));
            float e0v = __expf(s0 - m);
            float e1v = __expf(s1 - m);
            float sum = e0v + e1v;
            #pragma unroll
            for (int off = 16; off; off >>= 1)
                sum += __shfl_xor_sync(FULLMASK, sum, off);
            float inv = 1.0f / sum;
            s.sP[h * 64 + lane] = e0v * inv;
            s.sP[h * 64 + lane + 32] = e1v * inv;
        }
    }
    __syncthreads();

    // ---- PH7: V GEMM in registers + P-weighted accumulation ----
    if (gact) {
        const int e0 = etr * 4, d0 = dt * 4;
        u64 a0k[2] = {0, 0}, a1k[2] = {0, 0}, a2k[2] = {0, 0}, a3k[2] = {0, 0};
        #pragma unroll 4
        for (int k = 0; k < 64; k++) {
            u64 p01, p23; loadA(s.aT + k * AST + e0, p01, p23);
            float4 w = __ldg(reinterpret_cast<const float4*>(Wv + k * 64) + dt);
            u64 wx = dup2(w.x), wy = dup2(w.y), wz = dup2(w.z), ww = dup2(w.w);
            a0k[0] = fma2(p01, wx, a0k[0]);  a0k[1] = fma2(p23, wx, a0k[1]);
            a1k[0] = fma2(p01, wy, a1k[0]);  a1k[1] = fma2(p23, wy, a1k[1]);
            a2k[0] = fma2(p01, wz, a2k[0]);  a2k[1] = fma2(p23, wz, a2k[1]);
            a3k[0] = fma2(p01, ww, a3k[0]);  a3k[1] = fma2(p23, ww, a3k[1]);
        }
        const int h = dt >> 2;
        const float p0 = s.sP[h * 64 + e0];
        const float p1 = s.sP[h * 64 + e0 + 1];
        const float p2 = s.sP[h * 64 + e0 + 2];
        const float p3 = s.sP[h * 64 + e0 + 3];
        u64 accs[4][2] = {{a0k[0], a0k[1]}, {a1k[0], a1k[1]},
                          {a2k[0], a2k[1]}, {a3k[0], a3k[1]}};
        #pragma unroll
        for (int j = 0; j < 4; j++) {
            float2 v01 = unpack2(accs[j][0]);
            float2 v23 = unpack2(accs[j][1]);
            float op = p0 * v01.x + p1 * v01.y + p2 * v23.x + p3 * v23.y;
            atomicAdd(&s.sO[d0 + j], op);
        }
    }
    __syncthreads();

    // ---- PH8: epilogue (out @ Wc + ego) * 0.5 ----
    if (tid < 64) {
        const int d = tid;
        float a0 = 0.f, a1 = 0.f, a2 = 0.f, a3 = 0.f;
        #pragma unroll 4
        for (int k = 0; k < 64; k += 4) {
            a0 += s.sO[k]     * __ldg(Wc + (k)     * 64 + d);
            a1 += s.sO[k + 1] * __ldg(Wc + (k + 1) * 64 + d);
            a2 += s.sO[k + 2] * __ldg(Wc + (k + 2) * 64 + d);
            a3 += s.sO[k + 3] * __ldg(Wc + (k + 3) * 64 + d);
        }
        out[b * 64 + d] = (((a0 + a1) + (a2 + a3)) + s.sEgo[d]) * 0.5f;
    }
}

extern "C" void kernel_launch(void* const* d_in, const int* in_sizes, int n_in,
                              void* d_out, int out_size) {
    (void)in_sizes; (void)n_in; (void)out_size;
    const float* x      = (const float*)d_in[0];
    const float* ego_w0 = (const float*)d_in[1];
    const float* ego_b0 = (const float*)d_in[2];
    const float* ego_w1 = (const float*)d_in[3];
    const float* ego_b1 = (const float*)d_in[4];
    const float* oth_w0 = (const float*)d_in[5];
    const float* oth_b0 = (const float*)d_in[6];
    const float* oth_w1 = (const float*)d_in[7];
    const float* oth_b1 = (const float*)d_in[8];
    const float* Wk     = (const float*)d_in[9];
    const float* Wv     = (const float*)d_in[10];
    const float* Wq     = (const float*)d_in[11];
    const float* Wc     = (const float*)d_in[12];
    float* out = (float*)d_out;

    ego_attn_kernel<<<8192, NTHR>>>(x, ego_w0, ego_b0, ego_w1, ego_b1,
                                    oth_w0, oth_b0, oth_w1, oth_b1,
                                    Wk, Wv, Wq, Wc, out);
}

// round 5
// speedup vs baseline: 1.3974x; 1.2624x over previous
#include <cuda_runtime.h>

// EgoAttentionNetwork: B=8192, E=64, F_IN=7, D=64, H=4, HD=16
// One CTA per batch, 256 threads. Round-4:
//  - GEMM tiles 2 features x 4 entities (32 d-tiles x 8 e-warps): ~75% thread
//    utilization, whole-warp idling, 2-pass loop if >32 active entities.
//  - K and V GEMMs fused in one pass (scores via shfl, V^T to smem).
//  - unroll 8 on all strided weight-load chains (MLP ~8 vs L2 latency).

typedef unsigned long long u64;

#define AST 68
#define NTHR 256
#define FULLMASK 0xffffffffu

static __device__ __forceinline__ u64 fma2(u64 a, u64 b, u64 c) {
    u64 d;
    asm("fma.rn.f32x2 %0, %1, %2, %3;" : "=l"(d) : "l"(a), "l"(b), "l"(c));
    return d;
}
static __device__ __forceinline__ u64 dup2(float x) {
    u64 r;
    asm("mov.b64 %0, {%1, %1};" : "=l"(r) : "f"(x));
    return r;
}
static __device__ __forceinline__ float2 unpack2(u64 v) {
    float2 r;
    asm("mov.b64 {%0, %1}, %2;" : "=f"(r.x), "=f"(r.y) : "l"(v));
    return r;
}
static __device__ __forceinline__ void loadA(const float* p, u64& a, u64& b) {
    float4 v = *reinterpret_cast<const float4*>(p);
    asm("mov.b64 %0, {%1, %2};" : "=l"(a) : "f"(v.x), "f"(v.y));
    asm("mov.b64 %0, {%1, %2};" : "=l"(b) : "f"(v.z), "f"(v.w));
}

struct __align__(16) SmemT {
    float hT[64 * AST];   // hidden^T; reused as V^T after layer1
    float aT[64 * AST];   // input_all^T
    float sX[64 * 8];     // raw x rows (padded)
    float h0[64];         // ego hidden
    float sEgo[64];       // ego embedding
    float sQ[64];         // query
    float sO[64];         // attention out
    float sS[256];        // scores [4 heads][64]
    float sP[256];        // probs
    int   sIdx[64];
    int   nOth, uniformF, egoAct;
};

__global__ void __launch_bounds__(NTHR, 4)
ego_attn_kernel(const float* __restrict__ x,
                const float* __restrict__ ego_w0, const float* __restrict__ ego_b0,
                const float* __restrict__ ego_w1, const float* __restrict__ ego_b1,
                const float* __restrict__ oth_w0, const float* __restrict__ oth_b0,
                const float* __restrict__ oth_w1, const float* __restrict__ oth_b1,
                const float* __restrict__ Wk, const float* __restrict__ Wv,
                const float* __restrict__ Wq, const float* __restrict__ Wc,
                float* __restrict__ out)
{
    __shared__ SmemT s;
    const int tid = threadIdx.x;
    const int b = blockIdx.x;
    const int dt2 = tid & 31;             // 32 d-tiles of 2 features
    const int d0 = dt2 * 2;
    const int etw = tid >> 5;             // warp id = entity tile slot
    const int etr = (etw + (b & 7)) & 7;  // rotated entity tile
    const float* xb = x + b * 448;

    // ---- PH1: load x, init scores ----
    for (int idx = tid; idx < 448; idx += NTHR) {
        int e = idx / 7, f = idx % 7;
        s.sX[e * 8 + f] = __ldg(xb + idx);
    }
    s.sS[tid] = -1e30f;
    __syncthreads();

    // ---- PH2: compaction (warp0) | ego layer0 (warp1) ----
    if (tid < 32) {
        const int lane = tid;
        int egoA = (s.sX[0] >= 0.5f) ? 1 : 0;
        unsigned m1 = __ballot_sync(FULLMASK, (lane >= 1) && (s.sX[lane * 8] >= 0.5f));
        unsigned m2 = __ballot_sync(FULLMASK, s.sX[(lane + 32) * 8] >= 0.5f);
        int cnt = __popc(m1) + __popc(m2);
        unsigned lmask = (1u << lane) - 1u;
        if (cnt == 0 && !egoA) {
            // all masked -> uniform softmax over all 64 entities
            s.sIdx[lane] = lane + 1;
            if (lane < 31) s.sIdx[lane + 32] = lane + 33;
            if (lane == 0) { s.nOth = 63; s.uniformF = 1; s.egoAct = egoA; }
        } else {
            if ((lane >= 1) && (m1 >> lane & 1u))
                s.sIdx[__popc(m1 & lmask)] = lane;
            if (m2 >> lane & 1u)
                s.sIdx[__popc(m1) + __popc(m2 & lmask)] = lane + 32;
            if (lane == 0) { s.nOth = cnt; s.uniformF = 0; s.egoAct = egoA; }
        }
    } else if (tid < 64) {
        const int lane = tid - 32;
        #pragma unroll
        for (int r = 0; r < 2; r++) {
            int d = lane + r * 32;
            float acc = __ldg(ego_b0 + d);
            #pragma unroll
            for (int f = 0; f < 7; f++)
                acc += s.sX[f] * __ldg(ego_w0 + f * 64 + d);
            s.h0[d] = fmaxf(acc, 0.f);
        }
    }
    __syncthreads();

    const int nOth = s.nOth;
    const int uniformF = s.uniformF;
    const int egoAct = s.egoAct;
    const int cEgo = nOth;
    const int nTot = nOth + 1;
    int PADMAX = (nTot + 3) & ~3; if (PADMAX > 64) PADMAX = 64;
    const int nTiles = PADMAX >> 2;
    const int npass = (PADMAX + 31) >> 5;

    // ---- PH3: others layer0 (192 thr) | ego layer1 (64 thr, MLP 8) ----
    if (tid < 192) {
        const int total = nOth * 32;
        for (int idx = tid; idx < total; idx += 192) {
            int i = idx >> 5, dd = (idx & 31) * 2;
            int e = s.sIdx[i];
            const float* xr = s.sX + e * 8;
            float2 bb = *reinterpret_cast<const float2*>(oth_b0 + dd);
            float ax = bb.x, ay = bb.y;
            #pragma unroll
            for (int f = 0; f < 7; f++) {
                float2 w = __ldg(reinterpret_cast<const float2*>(oth_w0 + f * 64 + dd));
                float xv = xr[f];
                ax += xv * w.x; ay += xv * w.y;
            }
            s.hT[dd * AST + i]       = fmaxf(ax, 0.f);
            s.hT[(dd + 1) * AST + i] = fmaxf(ay, 0.f);
        }
    } else {
        const int d = tid - 192;
        float a0 = __ldg(ego_b1 + d), a1 = 0.f, a2 = 0.f, a3 = 0.f;
        #pragma unroll 8
        for (int k = 0; k < 64; k += 4) {
            a0 += s.h0[k]     * __ldg(ego_w1 + (k)     * 64 + d);
            a1 += s.h0[k + 1] * __ldg(ego_w1 + (k + 1) * 64 + d);
            a2 += s.h0[k + 2] * __ldg(ego_w1 + (k + 2) * 64 + d);
            a3 += s.h0[k + 3] * __ldg(ego_w1 + (k + 3) * 64 + d);
        }
        s.sEgo[d] = fmaxf((a0 + a1) + (a2 + a3), 0.f);
    }
    if (tid < 64) {
        for (int c = nOth; c < PADMAX; c++) s.hT[tid * AST + c] = 0.f;
    }
    __syncthreads();

    // ---- PH4: layer1 GEMM hT->aT (bias+relu+ego patch); free warps: q ----
    for (int ep = 0; ep < npass; ep++) {
        const int e0 = ep * 32 + etr * 4;
        if (e0 < PADMAX) {
            u64 a00 = 0, a01 = 0, a10 = 0, a11 = 0;
            #pragma unroll 8
            for (int k = 0; k < 64; k++) {
                u64 p01, p23; loadA(s.hT + k * AST + e0, p01, p23);
                float2 w = __ldg(reinterpret_cast<const float2*>(oth_w1 + k * 64 + d0));
                u64 wx = dup2(w.x), wy = dup2(w.y);
                a00 = fma2(p01, wx, a00);  a01 = fma2(p23, wx, a01);
                a10 = fma2(p01, wy, a10);  a11 = fma2(p23, wy, a11);
            }
            float b0v = __ldg(oth_b1 + d0);
            float b1v = __ldg(oth_b1 + d0 + 1);
            float2 c0 = unpack2(a00), c1 = unpack2(a01);
            float2 c2 = unpack2(a10), c3 = unpack2(a11);
            float r0[4] = { fmaxf(c0.x + b0v, 0.f), fmaxf(c0.y + b0v, 0.f),
                            fmaxf(c1.x + b0v, 0.f), fmaxf(c1.y + b0v, 0.f) };
            float r1[4] = { fmaxf(c2.x + b1v, 0.f), fmaxf(c2.y + b1v, 0.f),
                            fmaxf(c3.x + b1v, 0.f), fmaxf(c3.y + b1v, 0.f) };
            const int patch = cEgo - e0;
            if (patch >= 0 && patch < 4) {
                r0[patch] = s.sEgo[d0];
                r1[patch] = s.sEgo[d0 + 1];
            }
            *reinterpret_cast<float4*>(s.aT + d0 * AST + e0) =
                make_float4(r0[0], r0[1], r0[2], r0[3]);
            *reinterpret_cast<float4*>(s.aT + (d0 + 1) * AST + e0) =
                make_float4(r1[0], r1[1], r1[2], r1[3]);
        }
    }
    const bool canFreeQ = (nTiles <= 6);
    if (canFreeQ && etr >= nTiles && (etr - nTiles) < 2) {
        const int d = (etr - nTiles) * 32 + dt2;
        float a0 = 0.f, a1 = 0.f, a2 = 0.f, a3 = 0.f;
        #pragma unroll 8
        for (int k = 0; k < 64; k += 4) {
            a0 += s.sEgo[k]     * __ldg(Wq + (k)     * 64 + d);
            a1 += s.sEgo[k + 1] * __ldg(Wq + (k + 1) * 64 + d);
            a2 += s.sEgo[k + 2] * __ldg(Wq + (k + 2) * 64 + d);
            a3 += s.sEgo[k + 3] * __ldg(Wq + (k + 3) * 64 + d);
        }
        s.sQ[d] = (a0 + a1) + (a2 + a3);
    }
    __syncthreads();
    if (!canFreeQ) {
        if (tid < 64) {
            const int d = tid;
            float a0 = 0.f, a1 = 0.f, a2 = 0.f, a3 = 0.f;
            #pragma unroll 8
            for (int k = 0; k < 64; k += 4) {
                a0 += s.sEgo[k]     * __ldg(Wq + (k)     * 64 + d);
                a1 += s.sEgo[k + 1] * __ldg(Wq + (k + 1) * 64 + d);
                a2 += s.sEgo[k + 2] * __ldg(Wq + (k + 2) * 64 + d);
                a3 += s.sEgo[k + 3] * __ldg(Wq + (k + 3) * 64 + d);
            }
            s.sQ[d] = (a0 + a1) + (a2 + a3);
        }
        __syncthreads();
    }

    // ---- PH5: fused K+V GEMM; scores via shfl; V^T -> hT ----
    for (int ep = 0; ep < npass; ep++) {
        const int e0 = ep * 32 + etr * 4;
        if (e0 < PADMAX) {
            u64 k00 = 0, k01 = 0, k10 = 0, k11 = 0;
            u64 v00 = 0, v01 = 0, v10 = 0, v11 = 0;
            #pragma unroll 4
            for (int k = 0; k < 64; k++) {
                u64 p01, p23; loadA(s.aT + k * AST + e0, p01, p23);
                float2 wk = __ldg(reinterpret_cast<const float2*>(Wk + k * 64 + d0));
                float2 wv = __ldg(reinterpret_cast<const float2*>(Wv + k * 64 + d0));
                u64 kx = dup2(wk.x), ky = dup2(wk.y);
                u64 vx = dup2(wv.x), vy = dup2(wv.y);
                k00 = fma2(p01, kx, k00);  k01 = fma2(p23, kx, k01);
                k10 = fma2(p01, ky, k10);  k11 = fma2(p23, ky, k11);
                v00 = fma2(p01, vx, v00);  v01 = fma2(p23, vx, v01);
                v10 = fma2(p01, vy, v10);  v11 = fma2(p23, vy, v11);
            }
            // score partials over this thread's 2 features
            u64 q0 = dup2(s.sQ[d0]), q1 = dup2(s.sQ[d0 + 1]);
            u64 s01 = fma2(k00, q0, (u64)0), s23 = fma2(k01, q0, (u64)0);
            s01 = fma2(k10, q1, s01);        s23 = fma2(k11, q1, s23);
            float2 f01 = unpack2(s01), f23 = unpack2(s23);
            float sc0 = f01.x, sc1 = f01.y, sc2 = f23.x, sc3 = f23.y;
            // reduce over the 8 lanes (16 features) of each head
            #pragma unroll
            for (int o = 1; o < 8; o <<= 1) {
                sc0 += __shfl_xor_sync(FULLMASK, sc0, o);
                sc1 += __shfl_xor_sync(FULLMASK, sc1, o);
                sc2 += __shfl_xor_sync(FULLMASK, sc2, o);
                sc3 += __shfl_xor_sync(FULLMASK, sc3, o);
            }
            if ((dt2 & 7) == 0) {
                const int h = dt2 >> 3;
                float scv[4] = {sc0, sc1, sc2, sc3};
                #pragma unroll
                for (int m = 0; m < 4; m++) {
                    int col = e0 + m;
                    bool act = uniformF ? (col < nTot)
                                        : ((col < nOth) || (col == cEgo && egoAct));
                    s.sS[h * 64 + col] = act ? scv[m] * 0.25f : -1e30f;
                }
            }
            // store V^T rows d0, d0+1 (hT free after layer1)
            float2 va = unpack2(v00), vb = unpack2(v01);
            *reinterpret_cast<float4*>(s.hT + d0 * AST + e0) =
                make_float4(va.x, va.y, vb.x, vb.y);
            float2 vc = unpack2(v10), vd = unpack2(v11);
            *reinterpret_cast<float4*>(s.hT + (d0 + 1) * AST + e0) =
                make_float4(vc.x, vc.y, vd.x, vd.y);
        }
    }
    __syncthreads();

    // ---- PH6: softmax per head (warps 0-3) ----
    if (tid < 128) {
        const int h = tid >> 5, lane = tid & 31;
        if (uniformF) {
            const float p = 1.0f / 64.0f;
            s.sP[h * 64 + lane] = p;
            s.sP[h * 64 + lane + 32] = p;
        } else {
            float s0 = s.sS[h * 64 + lane];
            float s1 = s.sS[h * 64 + lane + 32];
            float m = fmaxf(s0, s1);
            #pragma unroll
            for (int off = 16; off; off >>= 1)
                m = fmaxf(m, __shfl_xor_sync(FULLMASK, m, off));
            float e0v = __expf(s0 - m);
            float e1v = __expf(s1 - m);
            float sum = e0v + e1v;
            #pragma unroll
            for (int off = 16; off; off >>= 1)
                sum += __shfl_xor_sync(FULLMASK, sum, off);
            float inv = 1.0f / sum;
            s.sP[h * 64 + lane] = e0v * inv;
            s.sP[h * 64 + lane + 32] = e1v * inv;
        }
    }
    __syncthreads();

    // ---- PH7: attention-weighted sum from V^T ----
    if (tid < 64) {
        const int d = tid, h = d >> 4;
        const float* pr = s.sP + h * 64;
        const float* vr = s.hT + d * AST;
        float a0 = 0.f, a1 = 0.f;
        for (int i = 0; i < PADMAX; i += 4) {
            float4 v = *reinterpret_cast<const float4*>(vr + i);
            a0 += pr[i] * v.x + pr[i + 1] * v.y;
            a1 += pr[i + 2] * v.z + pr[i + 3] * v.w;
        }
        s.sO[d] = a0 + a1;
    }
    __syncthreads();

    // ---- PH8: epilogue (out @ Wc + ego) * 0.5 ----
    if (tid < 64) {
        const int d = tid;
        float a0 = 0.f, a1 = 0.f, a2 = 0.f, a3 = 0.f;
        #pragma unroll 8
        for (int k = 0; k < 64; k += 4) {
            a0 += s.sO[k]     * __ldg(Wc + (k)     * 64 + d);
            a1 += s.sO[k + 1] * __ldg(Wc + (k + 1) * 64 + d);
            a2 += s.sO[k + 2] * __ldg(Wc + (k + 2) * 64 + d);
            a3 += s.sO[k + 3] * __ldg(Wc + (k + 3) * 64 + d);
        }
        out[b * 64 + d] = (((a0 + a1) + (a2 + a3)) + s.sEgo[d]) * 0.5f;
    }
}

extern "C" void kernel_launch(void* const* d_in, const int* in_sizes, int n_in,
                              void* d_out, int out_size) {
    (void)in_sizes; (void)n_in; (void)out_size;
    const float* x      = (const float*)d_in[0];
    const float* ego_w0 = (const float*)d_in[1];
    const float* ego_b0 = (const float*)d_in[2];
    const float* ego_w1 = (const float*)d_in[3];
    const float* ego_b1 = (const float*)d_in[4];
    const float* oth_w0 = (const float*)d_in[5];
    const float* oth_b0 = (const float*)d_in[6];
    const float* oth_w1 = (const float*)d_in[7];
    const float* oth_b1 = (const float*)d_in[8];
    const float* Wk     = (const float*)d_in[9];
    const float* Wv     = (const float*)d_in[10];
    const float* Wq     = (const float*)d_in[11];
    const float* Wc     = (const float*)d_in[12];
    float* out = (float*)d_out;

    ego_attn_kernel<<<8192, NTHR>>>(x, ego_w0, ego_b0, ego_w1, ego_b1,
                                    oth_w0, oth_b0, oth_w1, oth_b1,
                                    Wk, Wv, Wq, Wc, out);
}